// round 6
// baseline (speedup 1.0000x reference)
#include <cuda_runtime.h>
#include <cuda_bf16.h>
#include <math.h>
#include <stdint.h>
#include <stddef.h>

// ---------------- problem constants ----------------
#define T_STEPS 2048
#define BATCH   64
#define D_IN    512
#define D_HID   512
#define MROWS   (T_STEPS * BATCH)        // 131072
#define XCOLS   1536                     // r | z | g pre-activations from x

// ---------------- recurrent kernel topology ----------------
#define NGROUPS 4
#define CPG     32                       // CTAs per group
#define NCTAS   (NGROUPS * CPG)          // 128 (<= 148 SMs -> single wave)
#define BLOC    (BATCH / NGROUPS)        // 16 batches per group
#define RPC     (D_HID / CPG)            // 16 hidden rows per CTA per gate

// ---------------- device scratch (static; no allocation APIs) ----------------
__device__ float g_Xbuf[(size_t)MROWS * XCOLS];   // [t*64+b][1536]
__device__ float g_h[BATCH * D_HID];              // hidden state
__device__ float g_rh[BATCH * D_HID];             // r * h
__device__ unsigned int          g_cnt[NGROUPS];
__device__ volatile unsigned int g_gen[NGROUPS];

// =====================================================================
// zero the hidden state (runs each launch; g_h persists across replays)
// =====================================================================
__global__ void zero_h_kernel() {
    int i = blockIdx.x * blockDim.x + threadIdx.x;
    if (i < BATCH * D_HID) g_h[i] = 0.0f;
}

// =====================================================================
// Kernel A: input projection GEMM
//   g_Xbuf[m][gate*512+n] = x[m][:] . Wgate[n][0:512] + bias_gate[n]
// 128x128 block tile, BK=16, 256 threads, 8x8 per-thread microtile.
// =====================================================================
__global__ void __launch_bounds__(256, 2) xproj_kernel(
    const float* __restrict__ x,
    const float* __restrict__ Wr, const float* __restrict__ br,
    const float* __restrict__ Wz, const float* __restrict__ bz,
    const float* __restrict__ Wg, const float* __restrict__ bg)
{
    __shared__ float As[128][17];   // [m_local][k]  (pad 17: conflict-light)
    __shared__ float Bs[128][17];   // [n_local][k]

    const int bm = blockIdx.x;                 // 0..1023
    const int bn = blockIdx.y;                 // 0..11
    const int gate = bn >> 2;
    const int nb   = (bn & 3) << 7;            // row offset within gate
    const float* W    = (gate == 0) ? Wr : (gate == 1) ? Wz : Wg;
    const float* bias = (gate == 0) ? br : (gate == 1) ? bz : bg;
    const int m0 = bm << 7;

    const int tid = threadIdx.x;
    const int tx = tid & 15, ty = tid >> 4;
    const int lr  = tid >> 2;                  // 0..63
    const int lc4 = (tid & 3) << 2;            // 0,4,8,12

    float acc[8][8];
#pragma unroll
    for (int i = 0; i < 8; i++)
#pragma unroll
        for (int j = 0; j < 8; j++) acc[i][j] = 0.0f;

    for (int k0 = 0; k0 < 512; k0 += 16) {
        float4 a0 = *(const float4*)&x[(size_t)(m0 + lr)      * 512  + k0 + lc4];
        float4 a1 = *(const float4*)&x[(size_t)(m0 + lr + 64) * 512  + k0 + lc4];
        float4 w0 = *(const float4*)&W[(size_t)(nb + lr)      * 1024 + k0 + lc4];
        float4 w1 = *(const float4*)&W[(size_t)(nb + lr + 64) * 1024 + k0 + lc4];
        __syncthreads();
        As[lr][lc4 + 0] = a0.x; As[lr][lc4 + 1] = a0.y;
        As[lr][lc4 + 2] = a0.z; As[lr][lc4 + 3] = a0.w;
        As[lr + 64][lc4 + 0] = a1.x; As[lr + 64][lc4 + 1] = a1.y;
        As[lr + 64][lc4 + 2] = a1.z; As[lr + 64][lc4 + 3] = a1.w;
        Bs[lr][lc4 + 0] = w0.x; Bs[lr][lc4 + 1] = w0.y;
        Bs[lr][lc4 + 2] = w0.z; Bs[lr][lc4 + 3] = w0.w;
        Bs[lr + 64][lc4 + 0] = w1.x; Bs[lr + 64][lc4 + 1] = w1.y;
        Bs[lr + 64][lc4 + 2] = w1.z; Bs[lr + 64][lc4 + 3] = w1.w;
        __syncthreads();
#pragma unroll
        for (int kk = 0; kk < 16; kk++) {
            float a[8], b[8];
#pragma unroll
            for (int i = 0; i < 4; i++) {
                a[i]     = As[ty * 4 + i][kk];
                a[i + 4] = As[64 + ty * 4 + i][kk];
            }
#pragma unroll
            for (int j = 0; j < 4; j++) {
                b[j]     = Bs[tx * 4 + j][kk];
                b[j + 4] = Bs[64 + tx * 4 + j][kk];
            }
#pragma unroll
            for (int i = 0; i < 8; i++)
#pragma unroll
                for (int j = 0; j < 8; j++) acc[i][j] += a[i] * b[j];
        }
    }

    // epilogue: add bias, write float4s
    const int colbase = gate * 512 + nb;
#pragma unroll
    for (int i = 0; i < 8; i++) {
        int m = m0 + ((i < 4) ? (ty * 4 + i) : (64 + ty * 4 + (i - 4)));
        float4 v0, v1;
        v0.x = acc[i][0] + __ldg(&bias[nb + tx * 4 + 0]);
        v0.y = acc[i][1] + __ldg(&bias[nb + tx * 4 + 1]);
        v0.z = acc[i][2] + __ldg(&bias[nb + tx * 4 + 2]);
        v0.w = acc[i][3] + __ldg(&bias[nb + tx * 4 + 3]);
        v1.x = acc[i][4] + __ldg(&bias[nb + 64 + tx * 4 + 0]);
        v1.y = acc[i][5] + __ldg(&bias[nb + 64 + tx * 4 + 1]);
        v1.z = acc[i][6] + __ldg(&bias[nb + 64 + tx * 4 + 2]);
        v1.w = acc[i][7] + __ldg(&bias[nb + 64 + tx * 4 + 3]);
        *(float4*)&g_Xbuf[(size_t)m * XCOLS + colbase + tx * 4]      = v0;
        *(float4*)&g_Xbuf[(size_t)m * XCOLS + colbase + 64 + tx * 4] = v1;
    }
}

// =====================================================================
// group barrier: sense-reversing, generation-counted, 32 CTAs per group
// =====================================================================
__device__ __forceinline__ void group_barrier(int g) {
    __syncthreads();
    if (threadIdx.x == 0) {
        unsigned my = g_gen[g];
        __threadfence();                       // publish this CTA's STG writes
        unsigned a = atomicAdd(&g_cnt[g], 1u);
        if (a == CPG - 1) {
            g_cnt[g] = 0;
            __threadfence();
            g_gen[g] = my + 1;
        } else {
            while (g_gen[g] == my) { }
        }
        __threadfence();                       // acquire
    }
    __syncthreads();
}

__device__ __forceinline__ float dot4f(float4 a, float4 b) {
    return a.x * b.x + a.y * b.y + a.z * b.z + a.w * b.w;
}
__device__ __forceinline__ float sigmoidf_(float v) {
    return 1.0f / (1.0f + expf(-v));
}

// =====================================================================
// Kernel B: persistent recurrence. 128 CTAs x 256 threads, 1 CTA/SM.
// Group g (32 CTAs) owns batches [16g, 16g+16); CTA owns 16 hidden rows.
// =====================================================================
__global__ void __launch_bounds__(256, 1) gru_rec_kernel(
    float* __restrict__ out,
    const float* __restrict__ Wr,
    const float* __restrict__ Wz,
    const float* __restrict__ Wg)
{
    extern __shared__ float sm[];
    float* wrz = sm;                    // [32][512]  rows 0..15 Wr_h, 16..31 Wz_h
    float* wg  = wrz + 32 * 512;        // [16][512]  Wg_h
    float* hs  = wg  + 16 * 512;        // [16][512]  h (phase1) / r*h (phase2)
    float* zs  = hs  + 16 * 512;        // [16][16]   z for owned units
    float* hps = zs  + 256;             // [16][16]   h_prev for owned units

    const int cta = blockIdx.x;
    const int grp = cta >> 5;
    const int cid = cta & 31;
    const int n0 = cid * RPC;           // owned hidden rows [n0, n0+16)
    const int b0 = grp * BLOC;          // owned batches    [b0, b0+16)
    const int tid = threadIdx.x;

    // ---- load hidden-part weights into smem (once) ----
    for (int idx = tid; idx < 32 * 128; idx += 256) {       // float4 count
        int row = idx >> 7, c4 = idx & 127;
        const float* W = (row < 16) ? Wr : Wz;
        int n = n0 + (row & 15);
        ((float4*)wrz)[row * 128 + c4] =
            *(const float4*)&W[(size_t)n * 1024 + 512 + c4 * 4];
    }
    for (int idx = tid; idx < 16 * 128; idx += 256) {
        int row = idx >> 7, c4 = idx & 127;
        ((float4*)wg)[row * 128 + c4] =
            *(const float4*)&Wg[(size_t)(n0 + row) * 1024 + 512 + c4 * 4];
    }
    __syncthreads();

    // phase1 mapping: 32 tiles (4 btile x 8 ntile) x 8 k-chunks
    const int p1_tile = tid >> 3, p1_kc = tid & 7;
    const int p1_bb = (p1_tile >> 3) * 4;       // local batch base
    const int p1_rb = (p1_tile & 7) * 4;        // row base in 0..31 (r|z)
    // phase2 mapping: 16 tiles (4 btile x 4 ntile) x 16 k-chunks
    const int p2_tile = tid >> 4, p2_kc = tid & 15;
    const int p2_bb = (p2_tile >> 2) * 4;
    const int p2_rb = (p2_tile & 3) * 4;

    const float4* hs4  = (const float4*)hs;
    const float4* wrz4 = (const float4*)wrz;
    const float4* wg4  = (const float4*)wg;

    for (int t = 0; t < T_STEPS; t++) {
        const size_t xrow0 = (size_t)t * BATCH;

        // ---- stage h[b0..b0+15][0..511] (L2-coherent) ----
        for (int idx = tid; idx < 16 * 128; idx += 256) {
            int bl = idx >> 7, c4 = idx & 127;
            ((float4*)hs)[bl * 128 + c4] =
                __ldcg(&((const float4*)g_h)[(b0 + bl) * 128 + c4]);
        }
        __syncthreads();

        // ================= phase 1: r and z =================
        {
            float acc[16];
#pragma unroll
            for (int i = 0; i < 16; i++) acc[i] = 0.0f;
#pragma unroll 4
            for (int j = 0; j < 16; j++) {
                int o = p1_kc + j * 8;
                float4 hv[4], wv[4];
#pragma unroll
                for (int bb = 0; bb < 4; bb++) hv[bb] = hs4[(p1_bb + bb) * 128 + o];
#pragma unroll
                for (int rr = 0; rr < 4; rr++) wv[rr] = wrz4[(p1_rb + rr) * 128 + o];
#pragma unroll
                for (int bb = 0; bb < 4; bb++)
#pragma unroll
                    for (int rr = 0; rr < 4; rr++)
                        acc[bb * 4 + rr] += dot4f(hv[bb], wv[rr]);
            }
            // reduce across the 8 k-chunk lanes
#pragma unroll
            for (int i = 0; i < 16; i++) {
                float v = acc[i];
                v += __shfl_xor_sync(0xffffffffu, v, 1);
                v += __shfl_xor_sync(0xffffffffu, v, 2);
                v += __shfl_xor_sync(0xffffffffu, v, 4);
                acc[i] = v;
            }
            // each lane finalizes 2 of the tile's 16 outputs
#pragma unroll
            for (int u = 0; u < 2; u++) {
                int idx = p1_kc * 2 + u;
                int bb = idx >> 2, rr = idx & 3;
                int bl = p1_bb + bb;
                int b  = b0 + bl;
                int row = p1_rb + rr;                  // 0..15 r, 16..31 z
                float s = acc[bb * 4 + rr];
                size_t xr = (xrow0 + b) * (size_t)XCOLS;
                if (row < 16) {
                    int n = n0 + row;
                    float xv = __ldg(&g_Xbuf[xr + n]);
                    float rv = sigmoidf_(xv + s);
                    g_rh[b * 512 + n] = rv * hs[bl * 512 + n];
                } else {
                    int nl = row - 16;
                    int n  = n0 + nl;
                    float xv = __ldg(&g_Xbuf[xr + 512 + n]);
                    zs[bl * 16 + nl]  = sigmoidf_(xv + s);
                    hps[bl * 16 + nl] = hs[bl * 512 + n];
                }
            }
        }
        group_barrier(grp);     // all r*h for the group written

        // ---- stage r*h (overwrites hs) ----
        for (int idx = tid; idx < 16 * 128; idx += 256) {
            int bl = idx >> 7, c4 = idx & 127;
            ((float4*)hs)[bl * 128 + c4] =
                __ldcg(&((const float4*)g_rh)[(b0 + bl) * 128 + c4]);
        }
        __syncthreads();

        // ================= phase 2: g and h update =================
        {
            float acc[16];
#pragma unroll
            for (int i = 0; i < 16; i++) acc[i] = 0.0f;
#pragma unroll 4
            for (int j = 0; j < 8; j++) {
                int o = p2_kc + j * 16;
                float4 hv[4], wv[4];
#pragma unroll
                for (int bb = 0; bb < 4; bb++) hv[bb] = hs4[(p2_bb + bb) * 128 + o];
#pragma unroll
                for (int rr = 0; rr < 4; rr++) wv[rr] = wg4[(p2_rb + rr) * 128 + o];
#pragma unroll
                for (int bb = 0; bb < 4; bb++)
#pragma unroll
                    for (int rr = 0; rr < 4; rr++)
                        acc[bb * 4 + rr] += dot4f(hv[bb], wv[rr]);
            }
#pragma unroll
            for (int i = 0; i < 16; i++) {
                float v = acc[i];
                v += __shfl_xor_sync(0xffffffffu, v, 1);
                v += __shfl_xor_sync(0xffffffffu, v, 2);
                v += __shfl_xor_sync(0xffffffffu, v, 4);
                v += __shfl_xor_sync(0xffffffffu, v, 8);
                acc[i] = v;
            }
            {
                int idx = p2_kc;                       // 0..15 -> one output
                int bb = idx >> 2, rr = idx & 3;
                int bl = p2_bb + bb;
                int b  = b0 + bl;
                int nl = p2_rb + rr;
                int n  = n0 + nl;
                float s  = acc[bb * 4 + rr];
                float xv = __ldg(&g_Xbuf[(xrow0 + b) * (size_t)XCOLS + 1024 + n]);
                float gv = tanhf(xv + s);
                float zv = zs[bl * 16 + nl];
                float hp = hps[bl * 16 + nl];
                float hn = zv * hp + (1.0f - zv) * gv;
                g_h[b * 512 + n] = hn;
                out[((size_t)t * BATCH + b) * 512 + n] = hn;
            }
        }
        group_barrier(grp);     // h complete before next step's staging
    }
}

// =====================================================================
// optional tail: h_final after outs (if the output buffer includes it)
// =====================================================================
__global__ void copy_final_kernel(float* __restrict__ out) {
    int i = blockIdx.x * blockDim.x + threadIdx.x;
    if (i < BATCH * D_HID)
        out[(size_t)T_STEPS * BATCH * D_HID + i] = g_h[i];
}

// =====================================================================
extern "C" void kernel_launch(void* const* d_in, const int* in_sizes, int n_in,
                              void* d_out, int out_size) {
    const float* x  = (const float*)d_in[0];
    const float* Wr = (const float*)d_in[1];
    const float* br = (const float*)d_in[2];
    const float* Wz = (const float*)d_in[3];
    const float* bz = (const float*)d_in[4];
    const float* Wg = (const float*)d_in[5];
    const float* bg = (const float*)d_in[6];
    float* out = (float*)d_out;

    zero_h_kernel<<<(BATCH * D_HID + 255) / 256, 256>>>();

    dim3 gdim(MROWS / 128, XCOLS / 128);
    xproj_kernel<<<gdim, 256>>>(x, Wr, br, Wz, bz, Wg, bg);

    const int smem_bytes = (32 * 512 + 16 * 512 + 16 * 512 + 256 + 256) * 4; // 133120
    cudaFuncSetAttribute(gru_rec_kernel,
                         cudaFuncAttributeMaxDynamicSharedMemorySize, smem_bytes);
    gru_rec_kernel<<<NCTAS, 256, smem_bytes>>>(out, Wr, Wz, Wg);

    long long need = (long long)T_STEPS * BATCH * D_HID + (long long)BATCH * D_HID;
    if ((long long)out_size >= need)
        copy_final_kernel<<<(BATCH * D_HID + 255) / 256, 256>>>(out);
}

// round 7
// speedup vs baseline: 1.2522x; 1.2522x over previous
#include <cuda_runtime.h>
#include <cuda_bf16.h>
#include <math.h>
#include <stdint.h>
#include <stddef.h>

// ---------------- problem constants ----------------
#define T_STEPS 2048
#define BATCH   64
#define D_IN    512
#define D_HID   512
#define MROWS   (T_STEPS * BATCH)        // 131072
#define XCOLS   1536                     // r | z | g pre-activations from x

// ---------------- recurrent kernel topology ----------------
#define NGROUPS 8
#define CPG     16                       // CTAs per group
#define NCTAS   (NGROUPS * CPG)          // 128 (<= 148 SMs -> single wave)
#define BLOC    (BATCH / NGROUPS)        // 8 batches per group
#define RPC     (D_HID / CPG)            // 32 hidden rows per CTA per gate
#define RTHREADS 512

// ---------------- device scratch (static; no allocation APIs) ----------------
__device__ float g_Xbuf[(size_t)MROWS * XCOLS];   // [t*64+b][1536]
__device__ float g_h[BATCH * D_HID];              // hidden state
__device__ float g_rh[BATCH * D_HID];             // r * h
__device__ unsigned int          g_cnt[NGROUPS];
__device__ volatile unsigned int g_gen[NGROUPS];

// =====================================================================
__global__ void zero_h_kernel() {
    int i = blockIdx.x * blockDim.x + threadIdx.x;
    if (i < BATCH * D_HID) g_h[i] = 0.0f;
}

// =====================================================================
// Kernel A: input projection GEMM  (206 GFLOP, fp32)
//   g_Xbuf[m][gate*512+n] = x[m][:] . Wgate[n][0:512] + bias_gate[n]
// 128x128 tile, BK=16, 256 threads, 8x8 microtile, k-major smem,
// float4 fragments, double-buffered with register prefetch.
// =====================================================================
__global__ void __launch_bounds__(256, 2) xproj_kernel(
    const float* __restrict__ x,
    const float* __restrict__ Wr, const float* __restrict__ br,
    const float* __restrict__ Wz, const float* __restrict__ bz,
    const float* __restrict__ Wg, const float* __restrict__ bg)
{
    __shared__ float As[2][16][132];   // [buf][k][m]  (row stride 132 = 33*16B)
    __shared__ float Bs[2][16][132];   // [buf][k][n]

    const int bm = blockIdx.x;                 // 0..1023
    const int bn = blockIdx.y;                 // 0..11
    const int gate = bn >> 2;
    const int nb   = (bn & 3) << 7;
    const float* W    = (gate == 0) ? Wr : (gate == 1) ? Wz : Wg;
    const float* bias = (gate == 0) ? br : (gate == 1) ? bz : bg;
    const int m0 = bm << 7;

    const int tid = threadIdx.x;
    const int tx = tid & 15, ty = tid >> 4;
    const int lr  = tid >> 2;                  // 0..63
    const int lc4 = (tid & 3) << 2;            // 0,4,8,12

    const float* xa = x + (size_t)(m0 + lr)      * 512  + lc4;
    const float* xb = x + (size_t)(m0 + lr + 64) * 512  + lc4;
    const float* wa = W + (size_t)(nb + lr)      * 1024 + lc4;
    const float* wb = W + (size_t)(nb + lr + 64) * 1024 + lc4;

    float acc[8][8];
#pragma unroll
    for (int i = 0; i < 8; i++)
#pragma unroll
        for (int j = 0; j < 8; j++) acc[i][j] = 0.0f;

    // prologue: stage tile 0
    {
        float4 a0 = *(const float4*)xa;
        float4 a1 = *(const float4*)xb;
        float4 w0 = *(const float4*)wa;
        float4 w1 = *(const float4*)wb;
        const float av0[4] = {a0.x, a0.y, a0.z, a0.w};
        const float av1[4] = {a1.x, a1.y, a1.z, a1.w};
        const float wv0[4] = {w0.x, w0.y, w0.z, w0.w};
        const float wv1[4] = {w1.x, w1.y, w1.z, w1.w};
#pragma unroll
        for (int u = 0; u < 4; u++) {
            As[0][lc4 + u][lr]      = av0[u];
            As[0][lc4 + u][lr + 64] = av1[u];
            Bs[0][lc4 + u][lr]      = wv0[u];
            Bs[0][lc4 + u][lr + 64] = wv1[u];
        }
    }
    __syncthreads();

    int buf = 0;
#pragma unroll 1
    for (int t = 0; t < 32; t++) {
        float4 a0n, a1n, w0n, w1n;
        if (t < 31) {
            int k0 = (t + 1) << 4;
            a0n = *(const float4*)(xa + k0);
            a1n = *(const float4*)(xb + k0);
            w0n = *(const float4*)(wa + k0);
            w1n = *(const float4*)(wb + k0);
        }
#pragma unroll
        for (int kk = 0; kk < 16; kk++) {
            float4 av0 = *(const float4*)&As[buf][kk][ty * 4];
            float4 av1 = *(const float4*)&As[buf][kk][64 + ty * 4];
            float4 bv0 = *(const float4*)&Bs[buf][kk][tx * 4];
            float4 bv1 = *(const float4*)&Bs[buf][kk][64 + tx * 4];
            float a_[8] = {av0.x, av0.y, av0.z, av0.w, av1.x, av1.y, av1.z, av1.w};
            float b_[8] = {bv0.x, bv0.y, bv0.z, bv0.w, bv1.x, bv1.y, bv1.z, bv1.w};
#pragma unroll
            for (int i = 0; i < 8; i++)
#pragma unroll
                for (int j = 0; j < 8; j++) acc[i][j] += a_[i] * b_[j];
        }
        if (t < 31) {
            int nx = buf ^ 1;
            const float av0[4] = {a0n.x, a0n.y, a0n.z, a0n.w};
            const float av1[4] = {a1n.x, a1n.y, a1n.z, a1n.w};
            const float wv0[4] = {w0n.x, w0n.y, w0n.z, w0n.w};
            const float wv1[4] = {w1n.x, w1n.y, w1n.z, w1n.w};
#pragma unroll
            for (int u = 0; u < 4; u++) {
                As[nx][lc4 + u][lr]      = av0[u];
                As[nx][lc4 + u][lr + 64] = av1[u];
                Bs[nx][lc4 + u][lr]      = wv0[u];
                Bs[nx][lc4 + u][lr + 64] = wv1[u];
            }
        }
        __syncthreads();
        buf ^= 1;
    }

    // epilogue
    const int colbase = gate * 512 + nb;
#pragma unroll
    for (int i = 0; i < 8; i++) {
        int m = m0 + ((i < 4) ? (ty * 4 + i) : (64 + ty * 4 + (i - 4)));
        float4 v0, v1;
        v0.x = acc[i][0] + __ldg(&bias[nb + tx * 4 + 0]);
        v0.y = acc[i][1] + __ldg(&bias[nb + tx * 4 + 1]);
        v0.z = acc[i][2] + __ldg(&bias[nb + tx * 4 + 2]);
        v0.w = acc[i][3] + __ldg(&bias[nb + tx * 4 + 3]);
        v1.x = acc[i][4] + __ldg(&bias[nb + 64 + tx * 4 + 0]);
        v1.y = acc[i][5] + __ldg(&bias[nb + 64 + tx * 4 + 1]);
        v1.z = acc[i][6] + __ldg(&bias[nb + 64 + tx * 4 + 2]);
        v1.w = acc[i][7] + __ldg(&bias[nb + 64 + tx * 4 + 3]);
        *(float4*)&g_Xbuf[(size_t)m * XCOLS + colbase + tx * 4]      = v0;
        *(float4*)&g_Xbuf[(size_t)m * XCOLS + colbase + 64 + tx * 4] = v1;
    }
}

// =====================================================================
// group barrier: sense-reversing, 16 CTAs per group
// =====================================================================
__device__ __forceinline__ void group_barrier(int g) {
    __syncthreads();
    if (threadIdx.x == 0) {
        unsigned my = g_gen[g];
        __threadfence();
        unsigned a = atomicAdd(&g_cnt[g], 1u);
        if (a == CPG - 1) {
            g_cnt[g] = 0;
            __threadfence();
            g_gen[g] = my + 1;
        } else {
            while (g_gen[g] == my) { }
        }
        __threadfence();
    }
    __syncthreads();
}

__device__ __forceinline__ float dot4f(float4 a, float4 b) {
    return a.x * b.x + a.y * b.y + a.z * b.z + a.w * b.w;
}
__device__ __forceinline__ float fast_sigmoid(float v) {
    return 1.0f / (1.0f + __expf(-v));
}
__device__ __forceinline__ float fast_tanh(float v) {
    return 1.0f - 2.0f / (__expf(2.0f * v) + 1.0f);
}

// warp tree reduction: 32 accs over 32 lanes; lane l ends with full sum
// of acc index l (bit mapping: round off contributes `off` when lane&off).
__device__ __forceinline__ void reduce32(float* acc, int lane) {
#pragma unroll
    for (int off = 16; off >= 1; off >>= 1) {
        const int half = off;                    // cnt == 2*off each round
        const bool up = (lane & off) != 0;
#pragma unroll
        for (int i = 0; i < 16; i++) {
            if (i < half) {
                float send = up ? acc[i] : acc[i + half];
                float got  = __shfl_xor_sync(0xffffffffu, send, off);
                acc[i] = (up ? acc[i + half] : acc[i]) + got;
            }
        }
    }
}
// 16 accs over 32 lanes; lane pair {2o,2o+1} both end with sum of acc o=lane>>1.
__device__ __forceinline__ void reduce16dup(float* acc, int lane) {
#pragma unroll
    for (int off = 16; off >= 2; off >>= 1) {
        const int half = off >> 1;               // cnt == off each round
        const bool up = (lane & off) != 0;
#pragma unroll
        for (int i = 0; i < 8; i++) {
            if (i < half) {
                float send = up ? acc[i] : acc[i + half];
                float got  = __shfl_xor_sync(0xffffffffu, send, off);
                acc[i] = (up ? acc[i + half] : acc[i]) + got;
            }
        }
    }
    acc[0] += __shfl_xor_sync(0xffffffffu, acc[0], 1);
}

// =====================================================================
// Kernel B: persistent recurrence. 128 CTAs x 512 threads, 1 CTA/SM.
// Group g (16 CTAs) owns batches [8g, 8g+8); CTA owns 32 hidden rows.
// =====================================================================
__global__ void __launch_bounds__(RTHREADS, 1) gru_rec_kernel(
    float* __restrict__ out,
    const float* __restrict__ Wr,
    const float* __restrict__ Wz,
    const float* __restrict__ Wg)
{
    extern __shared__ float sm[];
    float* wrz = sm;                    // [64][512] rows 0..31 Wr_h, 32..63 Wz_h
    float* wg  = wrz + 64 * 512;        // [32][512] Wg_h
    float* hs  = wg  + 32 * 512;        // [8][512]  h (phase1) / r*h (phase2)
    float* zs  = hs  + 8 * 512;         // [8][32]
    float* hps = zs  + 256;             // [8][32]

    const int cta = blockIdx.x;
    const int grp = cta >> 4;
    const int cid = cta & 15;
    const int n0 = cid * RPC;           // owned hidden rows [n0, n0+32)
    const int b0 = grp * BLOC;          // owned batches    [b0, b0+8)
    const int tid = threadIdx.x;
    const int w = tid >> 5, lane = tid & 31;

    // ---- load hidden-part weights into smem (once) ----
    for (int idx = tid; idx < 64 * 128; idx += RTHREADS) {
        int row = idx >> 7, c4 = idx & 127;
        const float* W = (row < 32) ? Wr : Wz;
        int n = n0 + (row & 31);
        ((float4*)wrz)[idx] = *(const float4*)&W[(size_t)n * 1024 + 512 + c4 * 4];
    }
    for (int idx = tid; idx < 32 * 128; idx += RTHREADS) {
        int row = idx >> 7, c4 = idx & 127;
        ((float4*)wg)[idx] = *(const float4*)&Wg[(size_t)(n0 + row) * 1024 + 512 + c4 * 4];
    }
    __syncthreads();

    // phase1 per-lane output mapping: warp tile 4 batches x 8 rows
    const int p1_bb  = (w & 1) * 4;                    // local batch base
    const int p1_rb  = (w >> 1) * 8;                   // row base, 0..56 (r|z)
    const int p1_bl  = p1_bb + (lane >> 3);            // local batch 0..7
    const int p1_row = p1_rb + (lane & 7);             // 0..63
    const bool p1_isR = p1_row < 32;
    const int p1_nl  = p1_row & 31;
    const int p1_n   = n0 + p1_nl;
    const int p1_b   = b0 + p1_bl;
    const int p1_col = (p1_isR ? 0 : 512) + p1_n;
    // phase2: warp tile 2 batches x 8 rows; output o2 = lane>>1
    const int p2_bb = (w & 3) * 2;
    const int p2_rb = (w >> 2) * 8;
    const int o2    = lane >> 1;
    const int p2_bl = p2_bb + (o2 >> 3);
    const int p2_nl = p2_rb + (o2 & 7);
    const int p2_b  = b0 + p2_bl;
    const int p2_n  = n0 + p2_nl;

    const float4* hs4  = (const float4*)hs;
    const float4* wrz4 = (const float4*)wrz;
    const float4* wg4  = (const float4*)wg;

    const float* xrow = g_Xbuf;
    for (int t = 0; t < T_STEPS; t++, xrow += (size_t)BATCH * XCOLS) {
        // ---- prefetch this step's x pre-activations (hidden under compute) ----
        float x1v = __ldg(&xrow[(size_t)p1_b * XCOLS + p1_col]);
        float x2v = __ldg(&xrow[(size_t)p2_b * XCOLS + 1024 + p2_n]);

        // ---- stage h[b0..b0+7][:] (L2-coherent) ----
#pragma unroll
        for (int it = 0; it < 2; it++) {
            int idx = tid + it * RTHREADS;       // 0..1023
            ((float4*)hs)[idx] =
                __ldcg(&((const float4*)g_h)[b0 * 128 + idx]);
        }
        __syncthreads();

        // ================= phase 1: r and z =================
        {
            float acc[32];
#pragma unroll
            for (int i = 0; i < 32; i++) acc[i] = 0.0f;
#pragma unroll
            for (int j = 0; j < 4; j++) {
                const int o = lane + j * 32;
                float4 hv[4];
#pragma unroll
                for (int bbx = 0; bbx < 4; bbx++)
                    hv[bbx] = hs4[(p1_bb + bbx) * 128 + o];
#pragma unroll
                for (int rr = 0; rr < 8; rr++) {
                    float4 wv = wrz4[(p1_rb + rr) * 128 + o];
#pragma unroll
                    for (int bbx = 0; bbx < 4; bbx++)
                        acc[bbx * 8 + rr] += dot4f(hv[bbx], wv);
                }
            }
            reduce32(acc, lane);
            float pre = x1v + acc[0];
            float sg = fast_sigmoid(pre);
            if (p1_isR) {
                g_rh[p1_b * 512 + p1_n] = sg * hs[p1_bl * 512 + p1_n];
            } else {
                zs[p1_bl * 32 + p1_nl]  = sg;
                hps[p1_bl * 32 + p1_nl] = hs[p1_bl * 512 + p1_n];
            }
        }
        group_barrier(grp);     // all r*h for the group in L2

        // ---- stage r*h (overwrites hs) ----
#pragma unroll
        for (int it = 0; it < 2; it++) {
            int idx = tid + it * RTHREADS;
            ((float4*)hs)[idx] =
                __ldcg(&((const float4*)g_rh)[b0 * 128 + idx]);
        }
        __syncthreads();

        // ================= phase 2: g and h update =================
        {
            float acc[16];
#pragma unroll
            for (int i = 0; i < 16; i++) acc[i] = 0.0f;
#pragma unroll
            for (int j = 0; j < 4; j++) {
                const int o = lane + j * 32;
                float4 hv[2];
#pragma unroll
                for (int bbx = 0; bbx < 2; bbx++)
                    hv[bbx] = hs4[(p2_bb + bbx) * 128 + o];
#pragma unroll
                for (int rr = 0; rr < 8; rr++) {
                    float4 wv = wg4[(p2_rb + rr) * 128 + o];
#pragma unroll
                    for (int bbx = 0; bbx < 2; bbx++)
                        acc[bbx * 8 + rr] += dot4f(hv[bbx], wv);
                }
            }
            reduce16dup(acc, lane);
            if ((lane & 1) == 0) {
                float gv = fast_tanh(x2v + acc[0]);
                float zv = zs[p2_bl * 32 + p2_nl];
                float hp = hps[p2_bl * 32 + p2_nl];
                float hn = zv * hp + (1.0f - zv) * gv;
                g_h[p2_b * 512 + p2_n] = hn;
                out[((size_t)t * BATCH + p2_b) * 512 + p2_n] = hn;
            }
        }
        group_barrier(grp);     // h complete before next step's staging
    }
}

// =====================================================================
__global__ void copy_final_kernel(float* __restrict__ out) {
    int i = blockIdx.x * blockDim.x + threadIdx.x;
    if (i < BATCH * D_HID)
        out[(size_t)T_STEPS * BATCH * D_HID + i] = g_h[i];
}

// =====================================================================
extern "C" void kernel_launch(void* const* d_in, const int* in_sizes, int n_in,
                              void* d_out, int out_size) {
    const float* x  = (const float*)d_in[0];
    const float* Wr = (const float*)d_in[1];
    const float* br = (const float*)d_in[2];
    const float* Wz = (const float*)d_in[3];
    const float* bz = (const float*)d_in[4];
    const float* Wg = (const float*)d_in[5];
    const float* bg = (const float*)d_in[6];
    float* out = (float*)d_out;

    zero_h_kernel<<<(BATCH * D_HID + 255) / 256, 256>>>();

    dim3 gdim(MROWS / 128, XCOLS / 128);
    xproj_kernel<<<gdim, 256>>>(x, Wr, br, Wz, bz, Wg, bg);

    const int smem_bytes = (64 * 512 + 32 * 512 + 8 * 512 + 256 + 256) * 4; // 215040
    cudaFuncSetAttribute(gru_rec_kernel,
                         cudaFuncAttributeMaxDynamicSharedMemorySize, smem_bytes);
    gru_rec_kernel<<<NCTAS, RTHREADS, smem_bytes>>>(out, Wr, Wz, Wg);

    long long need = (long long)T_STEPS * BATCH * D_HID + (long long)BATCH * D_HID;
    if ((long long)out_size >= need)
        copy_final_kernel<<<(BATCH * D_HID + 255) / 256, 256>>>(out);
}